// round 8
// baseline (speedup 1.0000x reference)
#include <cuda_runtime.h>

#define SS 512
#define NUNITS 9
#define DSTRIDE 520   // 512 data + 8 zero pad; chunks 0..129
#define MAXB 128

__device__ float g_diag[MAXB * DSTRIDE];
__device__ float g_bias[SS * SS];

// Fused prep.
//  - diag blocks (low indices): gather diagonals, MLP=4 per thread.
//  - bias blocks: coalesced float4 -> smem -> conflict-free scalar reduce.
__global__ void prep_kernel(const float* __restrict__ in,
                            const float* __restrict__ bb,
                            int B, int ndiag_blocks) {
    __shared__ float sb[256 * 9];   // 9216 B
    if (blockIdx.x < (unsigned)ndiag_blocks) {
        int idx = blockIdx.x * blockDim.x + threadIdx.x;
        int bq = idx / DSTRIDE;
        int j  = idx - bq * DSTRIDE;
        int b4 = bq * 4;
        if (b4 >= B) return;
        float v[4] = {0.f, 0.f, 0.f, 0.f};
        bool jin = (j < SS);
#pragma unroll
        for (int k = 0; k < 4; k++) {
            if (jin && b4 + k < B)
                v[k] = __ldg(in + (size_t)(b4 + k) * SS * SS + (size_t)j * (SS + 1));
        }
#pragma unroll
        for (int k = 0; k < 4; k++) {
            if (b4 + k < B) g_diag[(size_t)(b4 + k) * DSTRIDE + j] = v[k];
        }
    } else {
        // 256 bias outputs per block; inputs 256*9 floats = 576 float4.
        int tid = threadIdx.x;
        int out0 = (blockIdx.x - ndiag_blocks) * 256;
        const float4* src = (const float4*)(bb + (size_t)out0 * 9);
        float4* s4 = (float4*)sb;
#pragma unroll
        for (int r = 0; r < 3; r++) {
            int k = tid + r * 256;
            if (k < 576) s4[k] = src[k];
        }
        __syncthreads();
        float acc = 0.0f;
#pragma unroll
        for (int t = 0; t < 9; t++) acc += sb[tid * 9 + t];   // 9t+i mod 32: conflict-free
        g_bias[out0 + tid] = acc;
    }
}

// Main kernel: lane L loads ONLY its own 16B chunk (coalesced LDG.128);
// window chunks +1/+2 arrive by warp shuffle (register crossbar -> zero L1
// wavefronts); warp-boundary chunks via 2 predicated 1-2 lane LDGs.
__global__ __launch_bounds__(128, 6)
void cnn_kernel(const float* __restrict__ w,
                float* __restrict__ out,
                int B, int bper) {
    int i    = blockIdx.x;          // 0..511
    int tid  = threadIdx.x;
    int lane = tid & 31;
    int j0   = tid << 2;            // chunk index = tid
    int b0 = blockIdx.y * bper;
    int b1 = b0 + bper;
    if (b1 > B) b1 = B;
    if (b0 >= b1) return;

    // ---- weights (masked, x9 folded) + bias prologue ----
    float wv[36];
    const float4* wp4 = (const float4*)(w + ((size_t)i * SS + j0) * NUNITS);
#pragma unroll
    for (int k = 0; k < 9; k++) {
        float4 q = wp4[k];
        wv[k * 4 + 0] = q.x; wv[k * 4 + 1] = q.y;
        wv[k * 4 + 2] = q.z; wv[k * 4 + 3] = q.w;
    }
#pragma unroll
    for (int n = 0; n < 36; n++) {
        int t = n % 9;                          // compile-time per n
        wv[n] *= (i + (t / 3) < SS) ? 9.0f : 0.0f;
    }
    float4 bias4 = *(const float4*)(g_bias + (size_t)i * SS + j0);

    const float* drow = g_diag + (size_t)b0 * DSTRIDE + j0;
    float* op = out + (size_t)b0 * (SS * SS) + (size_t)i * SS + j0;

    float4 e1 = make_float4(0.f, 0.f, 0.f, 0.f);   // lane 31: chunk +1
    float4 e2 = make_float4(0.f, 0.f, 0.f, 0.f);   // lanes 30,31: chunk +2
    const bool is31 = (lane == 31);
    const bool ge30 = (lane >= 30);

    for (int b = b0; b < b1; ++b) {
        float4 own = *(const float4*)drow;          // 4 wf (coalesced)
        if (is31) e1 = *(const float4*)(drow + 4);  // 1 wf
        if (ge30) e2 = *(const float4*)(drow + 8);  // 1 wf

        float4 n1, n2;
        n1.x = __shfl_down_sync(0xffffffffu, own.x, 1);
        n1.y = __shfl_down_sync(0xffffffffu, own.y, 1);
        n1.z = __shfl_down_sync(0xffffffffu, own.z, 1);
        n1.w = __shfl_down_sync(0xffffffffu, own.w, 1);
        n2.x = __shfl_down_sync(0xffffffffu, own.x, 2);
        n2.y = __shfl_down_sync(0xffffffffu, own.y, 2);
        n2.z = __shfl_down_sync(0xffffffffu, own.z, 2);
        n2.w = __shfl_down_sync(0xffffffffu, own.w, 2);

        float4 c1 = is31 ? e1 : n1;
        float4 c2 = ge30 ? e2 : n2;

        float d[12] = {own.x, own.y, own.z, own.w,
                       c1.x,  c1.y,  c1.z,  c1.w,
                       c2.x,  c2.y,  c2.z,  c2.w};

        float s0 = bias4.x, s1 = bias4.y, s2 = bias4.z, s3 = bias4.w;
#pragma unroll
        for (int t = 0; t < 9; t++) {
            s0 = fmaf(d[t],     wv[t],      s0);
            s1 = fmaf(d[t + 1], wv[9 + t],  s1);
            s2 = fmaf(d[t + 2], wv[18 + t], s2);
            s3 = fmaf(d[t + 3], wv[27 + t], s3);
        }
        float4 o; o.x = s0; o.y = s1; o.z = s2; o.w = s3;
        *(float4*)op = o;                           // 4 wf

        drow += DSTRIDE;
        op += SS * SS;
    }
}

extern "C" void kernel_launch(void* const* d_in, const int* in_sizes, int n_in,
                              void* d_out, int out_size) {
    const float* in = (const float*)d_in[0];   // inputs (B,512,512,1) f32
    const float* w  = (const float*)d_in[1];   // w (512*512*9,) f32
    const float* bb = (const float*)d_in[2];   // b (512*512*9,) f32
    float* out = (float*)d_out;                // (B, 512*512) f32

    int B = in_sizes[0] / (SS * SS);
    if (B > MAXB) B = MAXB;

    {
        int bq = (B + 3) / 4;
        int ndiag_blocks = (bq * DSTRIDE + 255) / 256;   // ~53
        int nbias_blocks = (SS * SS) / 256;              // 1024
        prep_kernel<<<ndiag_blocks + nbias_blocks, 256>>>(in, bb, B, ndiag_blocks);
    }

    const int NSLICE = 5;
    int bper = (B + NSLICE - 1) / NSLICE;
    dim3 grid(SS, NSLICE);                     // 2560 blocks
    cnn_kernel<<<grid, 128>>>(w, out, B, bper);
}

// round 9
// speedup vs baseline: 1.0352x; 1.0352x over previous
#include <cuda_runtime.h>

#define SS 512
#define NUNITS 9
#define DSTRIDE 520   // 512 data + 8 zero pad; 130 float4 per row
#define MAXB 128

__device__ float g_diag[MAXB * DSTRIDE];
__device__ float g_bias[SS * SS];

typedef unsigned long long ull;

__device__ __forceinline__ ull pk(float lo, float hi) {
    ull r;
    asm("mov.b64 %0, {%1, %2};" : "=l"(r) : "f"(lo), "f"(hi));
    return r;
}
__device__ __forceinline__ ull fma2(ull a, ull b, ull c) {
    ull d;
    asm("fma.rn.f32x2 %0, %1, %2, %3;" : "=l"(d) : "l"(a), "l"(b), "l"(c));
    return d;
}
__device__ __forceinline__ void upk(float& lo, float& hi, ull v) {
    asm("mov.b64 {%0, %1}, %2;" : "=f"(lo), "=f"(hi) : "l"(v));
}

// Fused prep: diag gather (MLP=4) on low blocks; bias reduction via
// coalesced float4 -> smem -> conflict-free scalar reads (9t+i mod 32).
__global__ void prep_kernel(const float* __restrict__ in,
                            const float* __restrict__ bb,
                            int B, int ndiag_blocks) {
    __shared__ float sb[256 * 9];
    if (blockIdx.x < (unsigned)ndiag_blocks) {
        int idx = blockIdx.x * blockDim.x + threadIdx.x;
        int bq = idx / DSTRIDE;
        int j  = idx - bq * DSTRIDE;
        int b4 = bq * 4;
        if (b4 >= B) return;
        float v[4] = {0.f, 0.f, 0.f, 0.f};
        bool jin = (j < SS);
#pragma unroll
        for (int k = 0; k < 4; k++) {
            if (jin && b4 + k < B)
                v[k] = __ldg(in + (size_t)(b4 + k) * SS * SS + (size_t)j * (SS + 1));
        }
#pragma unroll
        for (int k = 0; k < 4; k++) {
            if (b4 + k < B) g_diag[(size_t)(b4 + k) * DSTRIDE + j] = v[k];
        }
    } else {
        int tid = threadIdx.x;
        int out0 = (blockIdx.x - ndiag_blocks) * 256;
        const float4* src = (const float4*)(bb + (size_t)out0 * 9);
        float4* s4 = (float4*)sb;
#pragma unroll
        for (int r = 0; r < 3; r++) {
            int k = tid + r * 256;
            if (k < 576) s4[k] = src[k];
        }
        __syncthreads();
        float acc = 0.0f;
#pragma unroll
        for (int t = 0; t < 9; t++) acc += sb[tid * 9 + t];
        g_bias[out0 + tid] = acc;
    }
}

// Main kernel: R3 memory shape (3x LDG.128 + STG.128 per iter, 6 blk/SM),
// arithmetic switched to packed fma.rn.f32x2: 18 FFMA2 instead of 36 FFMA.
// acc01 lane0 = s(j0):   sum_t d[t]  *w[t]
// acc01 lane1 = s(j0+1): sum_t d[t+1]*w[9+t]   (pd[t] = (d[t],d[t+1]))
// acc23 uses pd[t+2] with (w[18+t],w[27+t]).
__global__ __launch_bounds__(128, 6)
void cnn_kernel(const float* __restrict__ w,
                float* __restrict__ out,
                int B, int bper) {
    int i  = blockIdx.x;          // 0..511
    int j0 = threadIdx.x << 2;    // 0,4,...,508
    int b0 = blockIdx.y * bper;
    int b1 = b0 + bper;
    if (b1 > B) b1 = B;
    if (b0 >= b1) return;

    // ---- prologue: load + mask weights, pack pairs ----
    float wv[36];
    const float4* wp4 = (const float4*)(w + ((size_t)i * SS + j0) * NUNITS);
#pragma unroll
    for (int k = 0; k < 9; k++) {
        float4 q = wp4[k];
        wv[k * 4 + 0] = q.x; wv[k * 4 + 1] = q.y;
        wv[k * 4 + 2] = q.z; wv[k * 4 + 3] = q.w;
    }
#pragma unroll
    for (int n = 0; n < 36; n++) {
        int t = n % 9;                          // compile-time per n
        wv[n] *= (i + (t / 3) < SS) ? 9.0f : 0.0f;
    }
    ull wp01[9], wp23[9];
#pragma unroll
    for (int t = 0; t < 9; t++) {
        wp01[t] = pk(wv[t],      wv[9 + t]);
        wp23[t] = pk(wv[18 + t], wv[27 + t]);
    }
    float4 bias4 = *(const float4*)(g_bias + (size_t)i * SS + j0);
    ull bias01 = pk(bias4.x, bias4.y);
    ull bias23 = pk(bias4.z, bias4.w);

    const float* drow = g_diag + (size_t)b0 * DSTRIDE + j0;
    float* op = out + (size_t)b0 * (SS * SS) + (size_t)i * SS + j0;

    for (int b = b0; b < b1; ++b) {
        const float4* dq = (const float4*)drow;
        float4 c0 = dq[0], c1 = dq[1], c2 = dq[2];

        // sliding pairs pd[t] = (d[t], d[t+1]); even ones are natural halves
        ull pd0  = pk(c0.x, c0.y), pd1 = pk(c0.y, c0.z);
        ull pd2  = pk(c0.z, c0.w), pd3 = pk(c0.w, c1.x);
        ull pd4  = pk(c1.x, c1.y), pd5 = pk(c1.y, c1.z);
        ull pd6  = pk(c1.z, c1.w), pd7 = pk(c1.w, c2.x);
        ull pd8  = pk(c2.x, c2.y), pd9 = pk(c2.y, c2.z);
        ull pd10 = pk(c2.z, c2.w);

        ull a01 = bias01, a23 = bias23;
        a01 = fma2(pd0, wp01[0], a01);  a23 = fma2(pd2,  wp23[0], a23);
        a01 = fma2(pd1, wp01[1], a01);  a23 = fma2(pd3,  wp23[1], a23);
        a01 = fma2(pd2, wp01[2], a01);  a23 = fma2(pd4,  wp23[2], a23);
        a01 = fma2(pd3, wp01[3], a01);  a23 = fma2(pd5,  wp23[3], a23);
        a01 = fma2(pd4, wp01[4], a01);  a23 = fma2(pd6,  wp23[4], a23);
        a01 = fma2(pd5, wp01[5], a01);  a23 = fma2(pd7,  wp23[5], a23);
        a01 = fma2(pd6, wp01[6], a01);  a23 = fma2(pd8,  wp23[6], a23);
        a01 = fma2(pd7, wp01[7], a01);  a23 = fma2(pd9,  wp23[7], a23);
        a01 = fma2(pd8, wp01[8], a01);  a23 = fma2(pd10, wp23[8], a23);

        float4 o;
        upk(o.x, o.y, a01);
        upk(o.z, o.w, a23);
        *(float4*)op = o;

        drow += DSTRIDE;
        op += SS * SS;
    }
}

extern "C" void kernel_launch(void* const* d_in, const int* in_sizes, int n_in,
                              void* d_out, int out_size) {
    const float* in = (const float*)d_in[0];   // inputs (B,512,512,1) f32
    const float* w  = (const float*)d_in[1];   // w (512*512*9,) f32
    const float* bb = (const float*)d_in[2];   // b (512*512*9,) f32
    float* out = (float*)d_out;                // (B, 512*512) f32

    int B = in_sizes[0] / (SS * SS);
    if (B > MAXB) B = MAXB;

    {
        int bq = (B + 3) / 4;
        int ndiag_blocks = (bq * DSTRIDE + 255) / 256;   // ~51
        int nbias_blocks = (SS * SS) / 256;              // 1024
        prep_kernel<<<ndiag_blocks + nbias_blocks, 256>>>(in, bb, B, ndiag_blocks);
    }

    const int NSLICE = 7;                      // 3584 blocks ~= 4.03 waves @ 6/SM
    int bper = (B + NSLICE - 1) / NSLICE;      // 15
    dim3 grid(SS, NSLICE);
    cnn_kernel<<<grid, 128>>>(w, out, B, bper);
}

// round 10
// speedup vs baseline: 1.1709x; 1.1311x over previous
#include <cuda_runtime.h>

#define SS 512
#define NUNITS 9
#define DSTRIDE 520   // 512 data + 8 zero pad; 130 float4 per row
#define MAXB 128

__device__ float g_diag[MAXB * DSTRIDE];
__device__ float g_bias[SS * SS];

// Fused prep: diag gather (MLP=4 per thread) on low blocks; bias reduction via
// coalesced float4 -> smem -> conflict-free scalar reads (9t+i mod 32, gcd=1).
__global__ void prep_kernel(const float* __restrict__ in,
                            const float* __restrict__ bb,
                            int B, int ndiag_blocks) {
    __shared__ float sb[256 * 9];
    if (blockIdx.x < (unsigned)ndiag_blocks) {
        int idx = blockIdx.x * blockDim.x + threadIdx.x;
        int bq = idx / DSTRIDE;
        int j  = idx - bq * DSTRIDE;
        int b4 = bq * 4;
        if (b4 >= B) return;
        float v[4] = {0.f, 0.f, 0.f, 0.f};
        bool jin = (j < SS);
#pragma unroll
        for (int k = 0; k < 4; k++) {
            if (jin && b4 + k < B)
                v[k] = __ldg(in + (size_t)(b4 + k) * SS * SS + (size_t)j * (SS + 1));
        }
#pragma unroll
        for (int k = 0; k < 4; k++) {
            if (b4 + k < B) g_diag[(size_t)(b4 + k) * DSTRIDE + j] = v[k];
        }
    } else {
        int tid = threadIdx.x;
        int out0 = (blockIdx.x - ndiag_blocks) * 256;
        const float4* src = (const float4*)(bb + (size_t)out0 * 9);
        float4* s4 = (float4*)sb;
#pragma unroll
        for (int r = 0; r < 3; r++) {
            int k = tid + r * 256;
            if (k < 576) s4[k] = src[k];
        }
        __syncthreads();
        float acc = 0.0f;
#pragma unroll
        for (int t = 0; t < 9; t++) acc += sb[tid * 9 + t];
        g_bias[out0 + tid] = acc;
    }
}

// Main kernel (R3 shape — measured 27.9us): thread owns (i, j0..j0+3) and a
// batch slice; 36 masked*9 weights live in registers; per iter 3x LDG.128 +
// 36 FMA + 1x STG.128. Launched with PDL: the weight prologue overlaps the
// prep kernel; cudaGridDependencySynchronize() gates the g_diag/g_bias reads.
__global__ __launch_bounds__(128, 6)
void cnn_kernel(const float* __restrict__ w,
                float* __restrict__ out,
                int B, int bper) {
    int i  = blockIdx.x;          // 0..511
    int j0 = threadIdx.x << 2;    // 0,4,...,508
    int b0 = blockIdx.y * bper;
    int b1 = b0 + bper;
    if (b1 > B) b1 = B;
    if (b0 >= b1) { cudaGridDependencySynchronize(); return; }

    // ---- prologue (independent of prep): 9x LDG.128 weights ----
    float wv[36];
    const float4* wp4 = (const float4*)(w + ((size_t)i * SS + j0) * NUNITS);
#pragma unroll
    for (int k = 0; k < 9; k++) {
        float4 q = wp4[k];
        wv[k * 4 + 0] = q.x; wv[k * 4 + 1] = q.y;
        wv[k * 4 + 2] = q.z; wv[k * 4 + 3] = q.w;
    }
#pragma unroll
    for (int n = 0; n < 36; n++) {
        int t = n % 9;                          // compile-time per n
        wv[n] *= (i + (t / 3) < SS) ? 9.0f : 0.0f;
    }

    // ---- wait for prep results, then read bias + diag ----
    cudaGridDependencySynchronize();

    float4 bias4 = *(const float4*)(g_bias + (size_t)i * SS + j0);

    const float* drow = g_diag + (size_t)b0 * DSTRIDE + j0;
    float* op = out + (size_t)b0 * (SS * SS) + (size_t)i * SS + j0;

    for (int b = b0; b < b1; ++b) {
        const float4* dq = (const float4*)drow;
        float4 c0 = dq[0], c1 = dq[1], c2 = dq[2];
        float d[12] = {c0.x, c0.y, c0.z, c0.w,
                       c1.x, c1.y, c1.z, c1.w,
                       c2.x, c2.y, c2.z, c2.w};

        float s0 = bias4.x, s1 = bias4.y, s2 = bias4.z, s3 = bias4.w;
#pragma unroll
        for (int t = 0; t < 9; t++) {
            s0 = fmaf(d[t],     wv[t],      s0);
            s1 = fmaf(d[t + 1], wv[9 + t],  s1);
            s2 = fmaf(d[t + 2], wv[18 + t], s2);
            s3 = fmaf(d[t + 3], wv[27 + t], s3);
        }
        float4 o; o.x = s0; o.y = s1; o.z = s2; o.w = s3;
        __stcs((float4*)op, o);                 // write-once: evict-first

        drow += DSTRIDE;
        op += SS * SS;
    }
}

extern "C" void kernel_launch(void* const* d_in, const int* in_sizes, int n_in,
                              void* d_out, int out_size) {
    const float* in = (const float*)d_in[0];   // inputs (B,512,512,1) f32
    const float* w  = (const float*)d_in[1];   // w (512*512*9,) f32
    const float* bb = (const float*)d_in[2];   // b (512*512*9,) f32
    float* out = (float*)d_out;                // (B, 512*512) f32

    int B = in_sizes[0] / (SS * SS);
    if (B > MAXB) B = MAXB;

    {
        int bq = (B + 3) / 4;
        int ndiag_blocks = (bq * DSTRIDE + 255) / 256;   // ~51
        int nbias_blocks = (SS * SS) / 256;              // 1024
        prep_kernel<<<ndiag_blocks + nbias_blocks, 256>>>(in, bb, B, ndiag_blocks);
    }

    const int NSLICE = 5;
    int bper = (B + NSLICE - 1) / NSLICE;      // 20
    dim3 grid(SS, NSLICE);                     // 2560 blocks

    // PDL: let cnn launch while prep drains; cnn's weight prologue overlaps
    // prep, and cudaGridDependencySynchronize() gates the dependent reads.
    cudaLaunchConfig_t cfg = {};
    cfg.gridDim = grid;
    cfg.blockDim = dim3(128, 1, 1);
    cfg.dynamicSmemBytes = 0;
    cfg.stream = 0;
    cudaLaunchAttribute attrs[1];
    attrs[0].id = cudaLaunchAttributeProgrammaticStreamSerialization;
    attrs[0].val.programmaticStreamSerializationAllowed = 1;
    cfg.attrs = attrs;
    cfg.numAttrs = 1;
    cudaError_t e = cudaLaunchKernelEx(&cfg, cnn_kernel, w, out, B, bper);
    if (e != cudaSuccess) {
        // Fallback: plain serial launch (still correct).
        cnn_kernel<<<grid, 128>>>(w, out, B, bper);
    }
}

// round 11
// speedup vs baseline: 1.3161x; 1.1240x over previous
#include <cuda_runtime.h>

#define SS 512
#define NUNITS 9
#define DSTRIDE 520   // 512 data + 8 zero pad; 130 float4 per row
#define MAXB 128

__device__ float g_diag[MAXB * DSTRIDE];
__device__ float g_bias[SS * SS];

// Fused prep: diag gather (MLP=4 per thread) on low blocks; bias reduction via
// coalesced float4 -> smem -> conflict-free scalar reads (9t+i mod 32).
__global__ void prep_kernel(const float* __restrict__ in,
                            const float* __restrict__ bb,
                            int B, int ndiag_blocks) {
    __shared__ float sb[256 * 9];
    if (blockIdx.x < (unsigned)ndiag_blocks) {
        int idx = blockIdx.x * blockDim.x + threadIdx.x;
        int bq = idx / DSTRIDE;
        int j  = idx - bq * DSTRIDE;
        int b4 = bq * 4;
        if (b4 >= B) return;
        float v[4] = {0.f, 0.f, 0.f, 0.f};
        bool jin = (j < SS);
#pragma unroll
        for (int k = 0; k < 4; k++) {
            if (jin && b4 + k < B)
                v[k] = __ldg(in + (size_t)(b4 + k) * SS * SS + (size_t)j * (SS + 1));
        }
#pragma unroll
        for (int k = 0; k < 4; k++) {
            if (b4 + k < B) g_diag[(size_t)(b4 + k) * DSTRIDE + j] = v[k];
        }
    } else {
        int tid = threadIdx.x;
        int out0 = (blockIdx.x - ndiag_blocks) * 256;
        const float4* src = (const float4*)(bb + (size_t)out0 * 9);
        float4* s4 = (float4*)sb;
#pragma unroll
        for (int r = 0; r < 3; r++) {
            int k = tid + r * 256;
            if (k < 576) s4[k] = src[k];
        }
        __syncthreads();
        float acc = 0.0f;
#pragma unroll
        for (int t = 0; t < 9; t++) acc += sb[tid * 9 + t];
        g_bias[out0 + tid] = acc;
    }
}

// Main kernel: R3 shape + per-block batch-phase rotation. Blocks start the
// batch loop at different rows, so co-resident blocks hit lines the leader
// already pulled into L1, and the chip-wide L2 hot-set widens by nb.
__global__ __launch_bounds__(128, 6)
void cnn_kernel(const float* __restrict__ w,
                float* __restrict__ out,
                int B, int bper) {
    int i  = blockIdx.x;          // 0..511
    int j0 = threadIdx.x << 2;    // 0,4,...,508
    int b0 = blockIdx.y * bper;
    int b1 = b0 + bper;
    if (b1 > B) b1 = B;
    if (b0 >= b1) { cudaGridDependencySynchronize(); return; }
    int nb = b1 - b0;

    // ---- prologue (independent of prep): 9x LDG.128 weights ----
    float wv[36];
    const float4* wp4 = (const float4*)(w + ((size_t)i * SS + j0) * NUNITS);
#pragma unroll
    for (int k = 0; k < 9; k++) {
        float4 q = wp4[k];
        wv[k * 4 + 0] = q.x; wv[k * 4 + 1] = q.y;
        wv[k * 4 + 2] = q.z; wv[k * 4 + 3] = q.w;
    }
#pragma unroll
    for (int n = 0; n < 36; n++) {
        int t = n % 9;                          // compile-time per n
        wv[n] *= (i + (t / 3) < SS) ? 9.0f : 0.0f;
    }

    // ---- wait for prep results ----
    cudaGridDependencySynchronize();

    float4 bias4 = *(const float4*)(g_bias + (size_t)i * SS + j0);

    const float* dbase = g_diag + (size_t)b0 * DSTRIDE + j0;
    float* obase = out + (size_t)b0 * (SS * SS) + (size_t)i * SS + j0;

    // rotation phase: decorrelate rows across blocks
    int idx = (blockIdx.x * 7) % nb;
    const float* drow = dbase + (size_t)idx * DSTRIDE;
    float* op = obase + (size_t)idx * (SS * SS);

    for (int lb = 0; lb < nb; ++lb) {
        const float4* dq = (const float4*)drow;
        float4 c0 = dq[0], c1 = dq[1], c2 = dq[2];
        float d[12] = {c0.x, c0.y, c0.z, c0.w,
                       c1.x, c1.y, c1.z, c1.w,
                       c2.x, c2.y, c2.z, c2.w};

        float s0 = bias4.x, s1 = bias4.y, s2 = bias4.z, s3 = bias4.w;
#pragma unroll
        for (int t = 0; t < 9; t++) {
            s0 = fmaf(d[t],     wv[t],      s0);
            s1 = fmaf(d[t + 1], wv[9 + t],  s1);
            s2 = fmaf(d[t + 2], wv[18 + t], s2);
            s3 = fmaf(d[t + 3], wv[27 + t], s3);
        }
        float4 o; o.x = s0; o.y = s1; o.z = s2; o.w = s3;
        __stcs((float4*)op, o);

        // advance with wrap
        ++idx;
        drow += DSTRIDE;
        op += SS * SS;
        if (idx == nb) {
            idx = 0;
            drow = dbase;
            op = obase;
        }
    }
}

extern "C" void kernel_launch(void* const* d_in, const int* in_sizes, int n_in,
                              void* d_out, int out_size) {
    const float* in = (const float*)d_in[0];   // inputs (B,512,512,1) f32
    const float* w  = (const float*)d_in[1];   // w (512*512*9,) f32
    const float* bb = (const float*)d_in[2];   // b (512*512*9,) f32
    float* out = (float*)d_out;                // (B, 512*512) f32

    int B = in_sizes[0] / (SS * SS);
    if (B > MAXB) B = MAXB;

    {
        int bq = (B + 3) / 4;
        int ndiag_blocks = (bq * DSTRIDE + 255) / 256;   // ~51
        int nbias_blocks = (SS * SS) / 256;              // 1024
        prep_kernel<<<ndiag_blocks + nbias_blocks, 256>>>(in, bb, B, ndiag_blocks);
    }

    const int NSLICE = 5;
    int bper = (B + NSLICE - 1) / NSLICE;      // 20
    dim3 grid(SS, NSLICE);                     // 2560 blocks

    cudaLaunchConfig_t cfg = {};
    cfg.gridDim = grid;
    cfg.blockDim = dim3(128, 1, 1);
    cfg.dynamicSmemBytes = 0;
    cfg.stream = 0;
    cudaLaunchAttribute attrs[1];
    attrs[0].id = cudaLaunchAttributeProgrammaticStreamSerialization;
    attrs[0].val.programmaticStreamSerializationAllowed = 1;
    cfg.attrs = attrs;
    cfg.numAttrs = 1;
    cudaError_t e = cudaLaunchKernelEx(&cfg, cnn_kernel, w, out, B, bper);
    if (e != cudaSuccess) {
        cnn_kernel<<<grid, 128>>>(w, out, B, bper);
    }
}

// round 12
// speedup vs baseline: 1.3174x; 1.0010x over previous
#include <cuda_runtime.h>

#define SS 512
#define NUNITS 9
#define DSTRIDE 520   // 512 data + 8 zero pad; 130 float4 per row
#define MAXB 128

__device__ float g_diag[MAXB * DSTRIDE];
__device__ float g_bias[SS * SS];

// Fused prep: diag gather (MLP=4 per thread) on low blocks; bias reduction via
// coalesced float4 -> smem -> conflict-free scalar reads (9t+i mod 32).
__global__ void prep_kernel(const float* __restrict__ in,
                            const float* __restrict__ bb,
                            int B, int ndiag_blocks) {
    __shared__ float sb[256 * 9];
    if (blockIdx.x < (unsigned)ndiag_blocks) {
        int idx = blockIdx.x * blockDim.x + threadIdx.x;
        int bq = idx / DSTRIDE;
        int j  = idx - bq * DSTRIDE;
        int b4 = bq * 4;
        if (b4 >= B) return;
        float v[4] = {0.f, 0.f, 0.f, 0.f};
        bool jin = (j < SS);
#pragma unroll
        for (int k = 0; k < 4; k++) {
            if (jin && b4 + k < B)
                v[k] = __ldg(in + (size_t)(b4 + k) * SS * SS + (size_t)j * (SS + 1));
        }
#pragma unroll
        for (int k = 0; k < 4; k++) {
            if (b4 + k < B) g_diag[(size_t)(b4 + k) * DSTRIDE + j] = v[k];
        }
    } else {
        int tid = threadIdx.x;
        int out0 = (blockIdx.x - ndiag_blocks) * 256;
        const float4* src = (const float4*)(bb + (size_t)out0 * 9);
        float4* s4 = (float4*)sb;
#pragma unroll
        for (int r = 0; r < 3; r++) {
            int k = tid + r * 256;
            if (k < 576) s4[k] = src[k];
        }
        __syncthreads();
        float acc = 0.0f;
#pragma unroll
        for (int t = 0; t < 9; t++) acc += sb[tid * 9 + t];
        g_bias[out0 + tid] = acc;
    }
}

// Main kernel: R3 shape + per-block batch-phase rotation + depth-1 software
// pipeline. Rotation decorrelates rows across blocks (L1/L2 reuse); the
// prefetch overlaps the remaining first-touch latency with the FMA block.
__global__ __launch_bounds__(128, 6)
void cnn_kernel(const float* __restrict__ w,
                float* __restrict__ out,
                int B, int bper) {
    int i  = blockIdx.x;          // 0..511
    int j0 = threadIdx.x << 2;    // 0,4,...,508
    int b0 = blockIdx.y * bper;
    int b1 = b0 + bper;
    if (b1 > B) b1 = B;
    if (b0 >= b1) { cudaGridDependencySynchronize(); return; }
    int nb = b1 - b0;

    // ---- prologue (independent of prep): 9x LDG.128 weights ----
    float wv[36];
    const float4* wp4 = (const float4*)(w + ((size_t)i * SS + j0) * NUNITS);
#pragma unroll
    for (int k = 0; k < 9; k++) {
        float4 q = wp4[k];
        wv[k * 4 + 0] = q.x; wv[k * 4 + 1] = q.y;
        wv[k * 4 + 2] = q.z; wv[k * 4 + 3] = q.w;
    }
#pragma unroll
    for (int n = 0; n < 36; n++) {
        int t = n % 9;                          // compile-time per n
        wv[n] *= (i + (t / 3) < SS) ? 9.0f : 0.0f;
    }

    // ---- wait for prep results ----
    cudaGridDependencySynchronize();

    float4 bias4 = *(const float4*)(g_bias + (size_t)i * SS + j0);

    const float* dbase = g_diag + (size_t)b0 * DSTRIDE + j0;
    float* obase = out + (size_t)b0 * (SS * SS) + (size_t)i * SS + j0;

    // rotation phase: decorrelate rows across blocks
    int idx = (blockIdx.x * 7) % nb;

    // prime the pipeline with row[idx]
    const float4* dq = (const float4*)(dbase + (size_t)idx * DSTRIDE);
    float4 c0 = dq[0], c1 = dq[1], c2 = dq[2];

    for (int lb = 0; lb < nb; ++lb) {
        // next row index (branch-free wrap)
        int nidx = idx + 1;
        nidx = (nidx == nb) ? 0 : nidx;

        // prefetch next row (issued before the FMA block consumes current)
        float4 n0, n1, n2;
        {
            const float4* nq = (const float4*)(dbase + (size_t)nidx * DSTRIDE);
            n0 = nq[0]; n1 = nq[1]; n2 = nq[2];
        }

        float d[12] = {c0.x, c0.y, c0.z, c0.w,
                       c1.x, c1.y, c1.z, c1.w,
                       c2.x, c2.y, c2.z, c2.w};

        float s0 = bias4.x, s1 = bias4.y, s2 = bias4.z, s3 = bias4.w;
#pragma unroll
        for (int t = 0; t < 9; t++) {
            s0 = fmaf(d[t],     wv[t],      s0);
            s1 = fmaf(d[t + 1], wv[9 + t],  s1);
            s2 = fmaf(d[t + 2], wv[18 + t], s2);
            s3 = fmaf(d[t + 3], wv[27 + t], s3);
        }
        float4 o; o.x = s0; o.y = s1; o.z = s2; o.w = s3;
        __stcs((float4*)(obase + (size_t)idx * (SS * SS)), o);

        c0 = n0; c1 = n1; c2 = n2;
        idx = nidx;
    }
}

extern "C" void kernel_launch(void* const* d_in, const int* in_sizes, int n_in,
                              void* d_out, int out_size) {
    const float* in = (const float*)d_in[0];   // inputs (B,512,512,1) f32
    const float* w  = (const float*)d_in[1];   // w (512*512*9,) f32
    const float* bb = (const float*)d_in[2];   // b (512*512*9,) f32
    float* out = (float*)d_out;                // (B, 512*512) f32

    int B = in_sizes[0] / (SS * SS);
    if (B > MAXB) B = MAXB;

    {
        int bq = (B + 3) / 4;
        int ndiag_blocks = (bq * DSTRIDE + 255) / 256;   // ~51
        int nbias_blocks = (SS * SS) / 256;              // 1024
        prep_kernel<<<ndiag_blocks + nbias_blocks, 256>>>(in, bb, B, ndiag_blocks);
    }

    const int NSLICE = 5;
    int bper = (B + NSLICE - 1) / NSLICE;      // 20
    dim3 grid(SS, NSLICE);                     // 2560 blocks

    cudaLaunchConfig_t cfg = {};
    cfg.gridDim = grid;
    cfg.blockDim = dim3(128, 1, 1);
    cfg.dynamicSmemBytes = 0;
    cfg.stream = 0;
    cudaLaunchAttribute attrs[1];
    attrs[0].id = cudaLaunchAttributeProgrammaticStreamSerialization;
    attrs[0].val.programmaticStreamSerializationAllowed = 1;
    cfg.attrs = attrs;
    cfg.numAttrs = 1;
    cudaError_t e = cudaLaunchKernelEx(&cfg, cnn_kernel, w, out, B, bper);
    if (e != cudaSuccess) {
        cnn_kernel<<<grid, 128>>>(w, out, B, bper);
    }
}

// round 13
// speedup vs baseline: 1.3282x; 1.0082x over previous
#include <cuda_runtime.h>

#define SS 512
#define NUNITS 9
#define DSTRIDE 520   // 512 data + 8 zero pad; 130 float4 per row
#define MAXB 128

__device__ float g_diag[MAXB * DSTRIDE];
__device__ float g_bias[SS * SS];

// Fused prep: diag gather (MLP=4 per thread) on low blocks; bias reduction via
// coalesced float4 -> smem -> conflict-free scalar reads (9t+i mod 32).
__global__ void prep_kernel(const float* __restrict__ in,
                            const float* __restrict__ bb,
                            int B, int ndiag_blocks) {
    __shared__ float sb[256 * 9];
    if (blockIdx.x < (unsigned)ndiag_blocks) {
        int idx = blockIdx.x * blockDim.x + threadIdx.x;
        int bq = idx / DSTRIDE;
        int j  = idx - bq * DSTRIDE;
        int b4 = bq * 4;
        if (b4 >= B) return;
        float v[4] = {0.f, 0.f, 0.f, 0.f};
        bool jin = (j < SS);
#pragma unroll
        for (int k = 0; k < 4; k++) {
            if (jin && b4 + k < B)
                v[k] = __ldg(in + (size_t)(b4 + k) * SS * SS + (size_t)j * (SS + 1));
        }
#pragma unroll
        for (int k = 0; k < 4; k++) {
            if (b4 + k < B) g_diag[(size_t)(b4 + k) * DSTRIDE + j] = v[k];
        }
    } else {
        int tid = threadIdx.x;
        int out0 = (blockIdx.x - ndiag_blocks) * 256;
        const float4* src = (const float4*)(bb + (size_t)out0 * 9);
        float4* s4 = (float4*)sb;
#pragma unroll
        for (int r = 0; r < 3; r++) {
            int k = tid + r * 256;
            if (k < 576) s4[k] = src[k];
        }
        __syncthreads();
        float acc = 0.0f;
#pragma unroll
        for (int t = 0; t < 9; t++) acc += sb[tid * 9 + t];
        g_bias[out0 + tid] = acc;
    }
}

// Main kernel: R3 memory shape + batch-phase rotation, NO prefetch (proven
// neutral; saves 8 regs) -> fits 72 regs -> 7 blocks/SM (28 warps, +17% TLP).
__global__ __launch_bounds__(128, 7)
void cnn_kernel(const float* __restrict__ w,
                float* __restrict__ out,
                int B, int bper) {
    int i  = blockIdx.x;          // 0..511
    int j0 = threadIdx.x << 2;    // 0,4,...,508
    int b0 = blockIdx.y * bper;
    int b1 = b0 + bper;
    if (b1 > B) b1 = B;
    if (b0 >= b1) { cudaGridDependencySynchronize(); return; }
    int nb = b1 - b0;

    // ---- prologue (independent of prep): 9x LDG.128 weights ----
    float wv[36];
    const float4* wp4 = (const float4*)(w + ((size_t)i * SS + j0) * NUNITS);
#pragma unroll
    for (int k = 0; k < 9; k++) {
        float4 q = wp4[k];
        wv[k * 4 + 0] = q.x; wv[k * 4 + 1] = q.y;
        wv[k * 4 + 2] = q.z; wv[k * 4 + 3] = q.w;
    }
#pragma unroll
    for (int n = 0; n < 36; n++) {
        int t = n % 9;                          // compile-time per n
        wv[n] *= (i + (t / 3) < SS) ? 9.0f : 0.0f;
    }

    // ---- wait for prep results ----
    cudaGridDependencySynchronize();

    float4 bias4 = *(const float4*)(g_bias + (size_t)i * SS + j0);

    const float* dbase = g_diag + (size_t)b0 * DSTRIDE + j0;
    float* obase = out + (size_t)b0 * (SS * SS) + (size_t)i * SS + j0;

    // rotation phase: decorrelate rows across blocks
    int idx = (blockIdx.x * 7) % nb;

    for (int lb = 0; lb < nb; ++lb) {
        const float4* dq = (const float4*)(dbase + (size_t)idx * DSTRIDE);
        float4 c0 = dq[0], c1 = dq[1], c2 = dq[2];
        float d[12] = {c0.x, c0.y, c0.z, c0.w,
                       c1.x, c1.y, c1.z, c1.w,
                       c2.x, c2.y, c2.z, c2.w};

        float s0 = bias4.x, s1 = bias4.y, s2 = bias4.z, s3 = bias4.w;
#pragma unroll
        for (int t = 0; t < 9; t++) {
            s0 = fmaf(d[t],     wv[t],      s0);
            s1 = fmaf(d[t + 1], wv[9 + t],  s1);
            s2 = fmaf(d[t + 2], wv[18 + t], s2);
            s3 = fmaf(d[t + 3], wv[27 + t], s3);
        }
        float4 o; o.x = s0; o.y = s1; o.z = s2; o.w = s3;
        __stcs((float4*)(obase + (size_t)idx * (SS * SS)), o);

        ++idx;
        idx = (idx == nb) ? 0 : idx;            // branch-free wrap (SEL)
    }
}

extern "C" void kernel_launch(void* const* d_in, const int* in_sizes, int n_in,
                              void* d_out, int out_size) {
    const float* in = (const float*)d_in[0];   // inputs (B,512,512,1) f32
    const float* w  = (const float*)d_in[1];   // w (512*512*9,) f32
    const float* bb = (const float*)d_in[2];   // b (512*512*9,) f32
    float* out = (float*)d_out;                // (B, 512*512) f32

    int B = in_sizes[0] / (SS * SS);
    if (B > MAXB) B = MAXB;

    {
        int bq = (B + 3) / 4;
        int ndiag_blocks = (bq * DSTRIDE + 255) / 256;   // ~51
        int nbias_blocks = (SS * SS) / 256;              // 1024
        prep_kernel<<<ndiag_blocks + nbias_blocks, 256>>>(in, bb, B, ndiag_blocks);
    }

    const int NSLICE = 6;                      // 3072 blocks ~= 2.97 waves @ 7/SM
    int bper = (B + NSLICE - 1) / NSLICE;      // 17
    dim3 grid(SS, NSLICE);

    cudaLaunchConfig_t cfg = {};
    cfg.gridDim = grid;
    cfg.blockDim = dim3(128, 1, 1);
    cfg.dynamicSmemBytes = 0;
    cfg.stream = 0;
    cudaLaunchAttribute attrs[1];
    attrs[0].id = cudaLaunchAttributeProgrammaticStreamSerialization;
    attrs[0].val.programmaticStreamSerializationAllowed = 1;
    cfg.attrs = attrs;
    cfg.numAttrs = 1;
    cudaError_t e = cudaLaunchKernelEx(&cfg, cnn_kernel, w, out, B, bper);
    if (e != cudaSuccess) {
        cnn_kernel<<<grid, 128>>>(w, out, B, bper);
    }
}